// round 9
// baseline (speedup 1.0000x reference)
#include <cuda_runtime.h>
#include <cuda_fp16.h>
#include <cstdint>

// ===========================================================================
// Kagome conv as implicit GEMM, fp16 single-pass mma.sync (fp32 accum).
// R9 vs R8 (L1/LSU-bound at 69.6%, tensor 35%):
//   - warp tile 32px x 64co (was 64x32): A-fragment loads per mma halved
//   - A smem layout interleaves the two k-halves -> 4 LDS.64 per iter
//     (was 16 LDS.32); stride 648==8 mod 32 -> conflict-free
//   - B: 4 coalesced LDG.128/iter, register double-buffer, distance 1
// ===========================================================================

__constant__ int FDR[37] = {1,1,2,3,4,4,6,7,8,10,11,12,14,14,15,16,17,17,16,15,14,14,12,10,8,6,4,4,3,2,5,9,13,15,17,15,13};
__constant__ int FDC[37] = {3,5,7,9,10,11,13,13,14,15,15,16,15,16,15,14,13,11,9,7,6,5,3,2,1,0,0,1,1,2,0,2,4,8,12,14,16};
__constant__ int FSR[37] = {13,13,14,15,16,16,6,7,8,10,11,12,2,2,3,4,5,5,4,3,2,2,12,10,8,6,16,16,15,14,5,9,1,3,5,3,1};
__constant__ int FSC[37] = {15,5,7,9,10,11,1,1,2,3,3,4,3,4,3,2,1,11,9,7,6,5,15,8,13,12,12,13,13,14,12,14,4,8,12,2,4};
// NOTE: FSC above must match reference exactly; value restored below in ctor check.
// (kept identical to prior rounds' verified table)
__constant__ int FSC_OK[37] = {15,5,7,9,10,11,1,1,2,3,3,4,3,4,3,2,1,11,9,7,6,5,15,14,13,12,12,13,13,14,12,14,4,8,12,2,4};

__constant__ unsigned MASKROW[16] = {
    0x0008u, 0x003Cu, 0x00FEu, 0x01FEu,
    0x0FFFu, 0x0FFFu, 0x0FFFu, 0x1FFEu,
    0x3FFCu, 0x3FFCu, 0x3FFCu, 0x7FF8u,
    0x7FF0u, 0x3FC0u, 0x1F00u, 0x1E00u
};

// W packed for N=64 warp tile: word w in lane-chunk of 16:
//   lanebase = ((u*2 + wn)*8 + lr)*4 + q,   u = tap*8 + g
//   w: kh = w>>3, ns = w&7
//   co = wn*64 + ns*8 + lr ; ci = g*16 + kh*8 + q*2 ; half2(ci, ci+1)
__device__ unsigned int Wf2[73728];

#define STR2 648                       // u32 row stride; 648%32==8
#define SMEM_BYTES (32 * STR2 * 4)     // 82,944 B

static __device__ __forceinline__ uint32_t packh2(float a, float b) {
    __half2 h = __floats2half2_rn(a, b);
    return *reinterpret_cast<uint32_t*>(&h);
}

static __device__ __forceinline__ void mma_fp16(float* c, const uint32_t* a,
                                                uint32_t b0, uint32_t b1) {
    asm volatile(
        "mma.sync.aligned.m16n8k16.row.col.f32.f16.f16.f32 "
        "{%0,%1,%2,%3}, {%4,%5,%6,%7}, {%8,%9}, {%0,%1,%2,%3};"
        : "+f"(c[0]), "+f"(c[1]), "+f"(c[2]), "+f"(c[3])
        : "r"(a[0]), "r"(a[1]), "r"(a[2]), "r"(a[3]), "r"(b0), "r"(b1));
}

// ---------------- prep: W -> Wf2 ----------------
__global__ void prep_w_kernel(const float* __restrict__ W) {
    int idx = blockIdx.x * 256 + threadIdx.x;
    if (idx >= 73728) return;
    int w  = idx & 15;
    int ns = w & 7;
    int kh = w >> 3;
    int lb = idx >> 4;
    int q  = lb & 3;
    int lr = (lb >> 2) & 7;
    int wn = (lb >> 5) & 1;
    int u  = lb >> 6;
    int tap = u >> 3, g = u & 7;
    int co = wn * 64 + ns * 8 + lr;
    int ci = g * 16 + kh * 8 + q * 2;
    Wf2[idx] = packh2(W[co * 1152 + ci * 9 + tap],
                      W[co * 1152 + (ci + 1) * 9 + tap]);
}

// ---------------- main ----------------
__global__ void __launch_bounds__(512, 1)
kagome_mma_kernel(const float* __restrict__ x,
                  const float* __restrict__ b,
                  float* __restrict__ out) {
    extern __shared__ uint32_t xph[];   // [32 gq][STR2]: word 2*pos+h

    const int tid   = threadIdx.x;
    const int wid   = tid >> 5;
    const int lane  = tid & 31;
    const int q     = lane & 3;
    const int lr    = lane >> 2;
    const int warpM = wid & 7;          // 8 groups of 2 image rows
    const int warpN = wid >> 3;         // 2 groups of 64 co
    const int img   = blockIdx.x;

    const float* xg = x + (size_t)img * 128 * 256;

    // ---- zero whole tile (borders must be 0) ----
    {
        uint4* z = (uint4*)xph;
        for (int j = tid; j < 32 * STR2 / 4; j += 512)
            z[j] = make_uint4(0, 0, 0, 0);
    }
    __syncthreads();
    // ---- interior ----
    #pragma unroll
    for (int i = 0; i < 8; i++) {
        int idx = tid + i * 512;            // 0..4095
        int p   = idx >> 6;                 // ci pair 0..63
        int px4 = (idx & 63) << 2;
        float4 r0 = *(const float4*)(xg + (2 * p) * 256 + px4);
        float4 r1 = *(const float4*)(xg + (2 * p + 1) * 256 + px4);
        int g = p >> 3, qq = p & 3, h = (p >> 2) & 1;
        uint32_t* base = xph + (g * 4 + qq) * STR2 + h;
        int pos = ((px4 >> 4) + 1) * 18 + (px4 & 15) + 1;
        base[2 * pos]     = packh2(r0.x, r1.x);
        base[2 * pos + 2] = packh2(r0.y, r1.y);
        base[2 * pos + 4] = packh2(r0.z, r1.z);
        base[2 * pos + 6] = packh2(r0.w, r1.w);
    }
    __syncthreads();   // interior visible before fixups overwrite
    // ---- 37 boundary fixups per ci pair ----
    for (int j = tid; j < 64 * 37; j += 512) {
        int p = j / 37, f = j - p * 37;
        int spx = (FSR[f] - 1) * 16 + (FSC_OK[f] - 1);
        int g = p >> 3, qq = p & 3, h = (p >> 2) & 1;
        xph[(g * 4 + qq) * STR2 + h + 2 * (FDR[f] * 18 + FDC[f])] =
            packh2(xg[(2 * p) * 256 + spx], xg[(2 * p + 1) * 256 + spx]);
    }
    __syncthreads();

    // ---- mainloop: 72 iterations ----
    float C[2][8][4];
    #pragma unroll
    for (int s = 0; s < 2; s++)
        #pragma unroll
        for (int n = 0; n < 8; n++)
            #pragma unroll
            for (int e = 0; e < 4; e++) C[s][n][e] = 0.f;

    const uint4* wlane = ((const uint4*)Wf2) + ((warpN * 8 + lr) * 4 + q) * 4;
    uint4 B[2][4];
    #pragma unroll
    for (int j = 0; j < 4; j++) B[0][j] = __ldg(wlane + j);

    #pragma unroll 1
    for (int u = 0; u < 72; u++) {
        const int tap = u >> 3, g = u & 7;
        const int kr = tap / 3, kc = tap - kr * 3;

        if (u < 71) {
            const uint4* wp = wlane + (u + 1) * 256;
            #pragma unroll
            for (int j = 0; j < 4; j++) B[(u + 1) & 1][j] = __ldg(wp + j);
        }
        uint4 b0 = B[u & 1][0];   // kh0 ns0-3
        uint4 b1 = B[u & 1][1];   // kh0 ns4-7
        uint4 b2 = B[u & 1][2];   // kh1 ns0-3
        uint4 b3 = B[u & 1][3];   // kh1 ns4-7

        const uint32_t* abase = xph + (g * 4 + q) * STR2;
        #pragma unroll
        for (int s = 0; s < 2; s++) {
            int R = warpM * 2 + s;
            int pos = (R + kr) * 18 + lr + kc;
            uint2 v0 = *(const uint2*)(abase + 2 * pos);        // m=lr
            uint2 v1 = *(const uint2*)(abase + 2 * pos + 16);   // m=lr+8
            uint32_t A[4] = {v0.x, v1.x, v0.y, v1.y};
            mma_fp16(C[s][0], A, b0.x, b2.x);
            mma_fp16(C[s][1], A, b0.y, b2.y);
            mma_fp16(C[s][2], A, b0.z, b2.z);
            mma_fp16(C[s][3], A, b0.w, b2.w);
            mma_fp16(C[s][4], A, b1.x, b3.x);
            mma_fp16(C[s][5], A, b1.y, b3.y);
            mma_fp16(C[s][6], A, b1.z, b3.z);
            mma_fp16(C[s][7], A, b1.w, b3.w);
        }
    }

    // ---- epilogue: +bias, *mask, store ----
    float* og = out + (size_t)img * 128 * 256;
    #pragma unroll
    for (int ns = 0; ns < 8; ns++) {
        int co0 = warpN * 64 + ns * 8 + 2 * q;
        float bv0 = __ldg(b + co0);
        float bv1 = __ldg(b + co0 + 1);
        #pragma unroll
        for (int s = 0; s < 2; s++) {
            int R = warpM * 2 + s;
            unsigned mrow = MASKROW[R];
            float k0 = ((mrow >> lr) & 1u) ? 1.f : 0.f;
            float k1 = ((mrow >> (lr + 8)) & 1u) ? 1.f : 0.f;
            int p0 = R * 16 + lr;
            int p1 = p0 + 8;
            og[co0 * 256 + p0]       = (C[s][ns][0] + bv0) * k0;
            og[(co0 + 1) * 256 + p0] = (C[s][ns][1] + bv1) * k0;
            og[co0 * 256 + p1]       = (C[s][ns][2] + bv0) * k1;
            og[(co0 + 1) * 256 + p1] = (C[s][ns][3] + bv1) * k1;
        }
    }
}

extern "C" void kernel_launch(void* const* d_in, const int* in_sizes, int n_in,
                              void* d_out, int out_size) {
    (void)in_sizes; (void)n_in; (void)out_size;
    const float* x = (const float*)d_in[0];
    const float* W = (const float*)d_in[1];
    const float* b = (const float*)d_in[2];
    float* out = (float*)d_out;

    cudaFuncSetAttribute(kagome_mma_kernel,
                         cudaFuncAttributeMaxDynamicSharedMemorySize, SMEM_BYTES);

    prep_w_kernel<<<288, 256>>>(W);
    kagome_mma_kernel<<<2048, 512, SMEM_BYTES>>>(x, b, out);
}

// round 10
// speedup vs baseline: 1.2643x; 1.2643x over previous
#include <cuda_runtime.h>
#include <cuda_fp16.h>
#include <cstdint>

// ===========================================================================
// Kagome conv as implicit GEMM, fp16 single-pass mma.sync (fp32 accum).
// R10 vs R8: co-dimension split across 2 CTAs per image -> C accumulators
// per thread drop 64 -> 32 floats, eliminating the register spills that
// R8/R9 (both pinned at the 128-reg cap) pushed into the L1 hot path.
// Warp tile 32px x 32co; A path identical to R8 (proven conflict-free);
// __launch_bounds__(512,2) targets occupancy 2 (2 x 82KB smem fits).
// ===========================================================================

__constant__ int FDR[37] = {1,1,2,3,4,4,6,7,8,10,11,12,14,14,15,16,17,17,16,15,14,14,12,10,8,6,4,4,3,2,5,9,13,15,17,15,13};
__constant__ int FDC[37] = {3,5,7,9,10,11,13,13,14,15,15,16,15,16,15,14,13,11,9,7,6,5,3,2,1,0,0,1,1,2,0,2,4,8,12,14,16};
__constant__ int FSR[37] = {13,13,14,15,16,16,6,7,8,10,11,12,2,2,3,4,5,5,4,3,2,2,12,10,8,6,16,16,15,14,5,9,1,3,5,3,1};
__constant__ int FSC[37] = {15,5,7,9,10,11,1,1,2,3,3,4,3,4,3,2,1,11,9,7,6,5,15,14,13,12,12,13,13,14,12,14,4,8,12,2,4};

__constant__ unsigned MASKROW[16] = {
    0x0008u, 0x003Cu, 0x00FEu, 0x01FEu,
    0x0FFFu, 0x0FFFu, 0x0FFFu, 0x1FFEu,
    0x3FFCu, 0x3FFCu, 0x3FFCu, 0x7FF8u,
    0x7FF0u, 0x3FC0u, 0x1F00u, 0x1E00u
};

// W packed (same as R8): index = ((((tap*8+g)*4+wn)*8+lr)*8+kq)*4+ns
// u32 = half2(ci, ci+1), co = wn*32+ns*8+lr, ci = g*16+2*kq.
__device__ unsigned int Wf[9 * 8 * 4 * 8 * 8 * 4];   // 73728 u32

#define PSTR 328                      // pos stride (u32); 328%32==8
#define SMEM_BYTES (64 * PSTR * 4)    // 83,968 B

static __device__ __forceinline__ uint32_t packh2(float a, float b) {
    __half2 h = __floats2half2_rn(a, b);
    return *reinterpret_cast<uint32_t*>(&h);
}

static __device__ __forceinline__ void mma_fp16(float* c, const uint32_t* a,
                                                uint32_t b0, uint32_t b1) {
    asm volatile(
        "mma.sync.aligned.m16n8k16.row.col.f32.f16.f16.f32 "
        "{%0,%1,%2,%3}, {%4,%5,%6,%7}, {%8,%9}, {%0,%1,%2,%3};"
        : "+f"(c[0]), "+f"(c[1]), "+f"(c[2]), "+f"(c[3])
        : "r"(a[0]), "r"(a[1]), "r"(a[2]), "r"(a[3]), "r"(b0), "r"(b1));
}

// ---------------- prep: W -> Wf (unchanged from R8) ----------------
__global__ void prep_w_kernel(const float* __restrict__ W) {
    int idx = blockIdx.x * 256 + threadIdx.x;
    if (idx >= 73728) return;
    int ns  = idx & 3;
    int kq  = (idx >> 2) & 7;
    int lr  = (idx >> 5) & 7;
    int wn  = (idx >> 8) & 3;
    int g   = (idx >> 10) & 7;
    int tap = idx >> 13;
    int co  = wn * 32 + ns * 8 + lr;
    int ci  = g * 16 + kq * 2;
    Wf[idx] = packh2(W[co * 1152 + ci * 9 + tap],
                     W[co * 1152 + (ci + 1) * 9 + tap]);
}

// ---------------- main ----------------
__global__ void __launch_bounds__(512, 2)
kagome_mma_kernel(const float* __restrict__ x,
                  const float* __restrict__ b,
                  float* __restrict__ out) {
    extern __shared__ uint32_t xph[];   // [64 ci-pair][PSTR pos]

    const int tid   = threadIdx.x;
    const int wid   = tid >> 5;
    const int lane  = tid & 31;
    const int q     = lane & 3;
    const int lr    = lane >> 2;
    const int warpM = wid & 7;          // 8 groups of 2 image rows (32 px)
    const int warpN = wid >> 3;         // 2 groups of 32 co within this half
    const int wn    = blockIdx.x * 2 + warpN;   // global co group 0..3
    const int img   = blockIdx.y;

    const float* xg = x + (size_t)img * 128 * 256;

    // ---- zero whole tile (borders must be 0) ----
    {
        uint4* z = (uint4*)xph;
        for (int j = tid; j < 64 * PSTR / 4; j += 512)
            z[j] = make_uint4(0, 0, 0, 0);
    }
    __syncthreads();
    // ---- interior: (pair p, px quad) — identical to R8 ----
    #pragma unroll
    for (int i = 0; i < 8; i++) {
        int idx = tid + i * 512;            // 0..4095
        int p   = idx >> 6;                 // ci pair 0..63
        int px4 = (idx & 63) << 2;          // 0,4,...,252
        float4 r0 = *(const float4*)(xg + (2 * p) * 256 + px4);
        float4 r1 = *(const float4*)(xg + (2 * p + 1) * 256 + px4);
        int pos = ((px4 >> 4) + 1) * 18 + (px4 & 15) + 1;
        uint32_t* d = xph + p * PSTR + pos;
        d[0] = packh2(r0.x, r1.x);
        d[1] = packh2(r0.y, r1.y);
        d[2] = packh2(r0.z, r1.z);
        d[3] = packh2(r0.w, r1.w);
    }
    __syncthreads();   // interior visible before fixups overwrite
    // ---- 37 boundary fixups per ci pair ----
    for (int j = tid; j < 64 * 37; j += 512) {
        int p = j / 37, f = j - p * 37;
        int spx = (FSR[f] - 1) * 16 + (FSC[f] - 1);
        uint32_t v = packh2(xg[(2 * p) * 256 + spx], xg[(2 * p + 1) * 256 + spx]);
        xph[p * PSTR + FDR[f] * 18 + FDC[f]] = v;
    }
    __syncthreads();

    // ---- mainloop: 72 iterations (9 taps x 8 ci-groups) ----
    float C[2][4][4];
    #pragma unroll
    for (int s = 0; s < 2; s++)
        #pragma unroll
        for (int n = 0; n < 4; n++)
            #pragma unroll
            for (int e = 0; e < 4; e++) C[s][n][e] = 0.f;

    const uint32_t* wbase = Wf + ((wn * 8) + lr) * 32 + q * 4;
    // register double-buffer, prefetch distance 2; u-loop unrolled by 2
    // so all buffer indices are static (no local-memory demotion).
    uint4 Bs[2][2];
    Bs[0][0] = __ldg((const uint4*)(wbase));
    Bs[0][1] = __ldg((const uint4*)(wbase + 16));
    Bs[1][0] = __ldg((const uint4*)(wbase + 1024));
    Bs[1][1] = __ldg((const uint4*)(wbase + 1024 + 16));

    #pragma unroll 2
    for (int u = 0; u < 72; u++) {
        const int tap = u >> 3, g = u & 7;
        const int kr = (tap >= 6) ? 2 : (tap >= 3 ? 1 : 0);
        const int kc = tap - kr * 3;

        uint4 b0 = Bs[u & 1][0];
        uint4 b1 = Bs[u & 1][1];
        if (u < 70) {
            const uint32_t* wp = wbase + (u + 2) * 1024;
            Bs[u & 1][0] = __ldg((const uint4*)(wp));
            Bs[u & 1][1] = __ldg((const uint4*)(wp + 16));
        }

        const uint32_t* aslot = xph + (g * 8 + q) * PSTR;
        #pragma unroll
        for (int s = 0; s < 2; s++) {
            int R = warpM * 2 + s;
            int pos = (R + kr) * 18 + lr + kc;
            uint32_t A[4];
            A[0] = aslot[pos];                 // m=lr,   k 2q,2q+1
            A[1] = aslot[pos + 8];             // m=lr+8, k 2q,2q+1
            A[2] = aslot[4 * PSTR + pos];      // m=lr,   k 2q+8,2q+9
            A[3] = aslot[4 * PSTR + pos + 8];  // m=lr+8, k 2q+8,2q+9
            mma_fp16(C[s][0], A, b0.x, b1.x);
            mma_fp16(C[s][1], A, b0.y, b1.y);
            mma_fp16(C[s][2], A, b0.z, b1.z);
            mma_fp16(C[s][3], A, b0.w, b1.w);
        }
    }

    // ---- epilogue: +bias, *mask, store ----
    float* og = out + (size_t)img * 128 * 256;
    #pragma unroll
    for (int ns = 0; ns < 4; ns++) {
        int co0 = wn * 32 + ns * 8 + 2 * q;
        float bv0 = __ldg(b + co0);
        float bv1 = __ldg(b + co0 + 1);
        #pragma unroll
        for (int s = 0; s < 2; s++) {
            int R = warpM * 2 + s;
            unsigned mrow = MASKROW[R];
            float k0 = ((mrow >> lr) & 1u) ? 1.f : 0.f;
            float k1 = ((mrow >> (lr + 8)) & 1u) ? 1.f : 0.f;
            int p0 = R * 16 + lr;
            int p1 = p0 + 8;
            og[co0 * 256 + p0]       = (C[s][ns][0] + bv0) * k0;
            og[(co0 + 1) * 256 + p0] = (C[s][ns][1] + bv1) * k0;
            og[co0 * 256 + p1]       = (C[s][ns][2] + bv0) * k1;
            og[(co0 + 1) * 256 + p1] = (C[s][ns][3] + bv1) * k1;
        }
    }
}

extern "C" void kernel_launch(void* const* d_in, const int* in_sizes, int n_in,
                              void* d_out, int out_size) {
    (void)in_sizes; (void)n_in; (void)out_size;
    const float* x = (const float*)d_in[0];
    const float* W = (const float*)d_in[1];
    const float* b = (const float*)d_in[2];
    float* out = (float*)d_out;

    cudaFuncSetAttribute(kagome_mma_kernel,
                         cudaFuncAttributeMaxDynamicSharedMemorySize, SMEM_BYTES);

    prep_w_kernel<<<288, 256>>>(W);
    dim3 grid(2, 2048);
    kagome_mma_kernel<<<grid, 512, SMEM_BYTES>>>(x, b, out);
}

// round 11
// speedup vs baseline: 2.4166x; 1.9114x over previous
#include <cuda_runtime.h>
#include <cuda_fp16.h>
#include <cstdint>

// ===========================================================================
// Kagome conv as implicit GEMM, fp16 single-pass mma.sync (fp32 accum).
// R11 = R8 with the A-path rebuilt around ldmatrix:
//   - image tile pos-major: xpm[324 pos][68 u32], u32 j = half2(ci 2j,2j+1)
//   - A fragment = 1 ldmatrix.x4 per m16 subtile (was 4 LDS.32) ->
//     per warp-iter A instructions 16 -> 4; banks conflict-free (stride
//     68 % 32 == 4: 8-row phases cover all 32 banks)
//   - B path / warp tiling (64px x 32co) / epilogue identical to R8
// ===========================================================================

__constant__ int FDR[37] = {1,1,2,3,4,4,6,7,8,10,11,12,14,14,15,16,17,17,16,15,14,14,12,10,8,6,4,4,3,2,5,9,13,15,17,15,13};
__constant__ int FDC[37] = {3,5,7,9,10,11,13,13,14,15,15,16,15,16,15,14,13,11,9,7,6,5,3,2,1,0,0,1,1,2,0,2,4,8,12,14,16};
__constant__ int FSR[37] = {13,13,14,15,16,16,6,7,8,10,11,12,2,2,3,4,5,5,4,3,2,2,12,10,8,6,16,16,15,14,5,9,1,3,5,3,1};
__constant__ int FSC[37] = {15,5,7,9,10,11,1,1,2,3,3,4,3,4,3,2,1,11,9,7,6,5,15,14,13,12,12,13,13,14,12,14,4,8,12,2,4};

__constant__ unsigned MASKROW[16] = {
    0x0008u, 0x003Cu, 0x00FEu, 0x01FEu,
    0x0FFFu, 0x0FFFu, 0x0FFFu, 0x1FFEu,
    0x3FFCu, 0x3FFCu, 0x3FFCu, 0x7FF8u,
    0x7FF0u, 0x3C0u | 0x3C00u, 0x1F00u, 0x1E00u
};
// NOTE row 13 mask: 0x3FC0 (bits 6..13). Expressed oddly above; fixed here:
__constant__ unsigned MASKROW_FIX = 0x3FC0u;

// W packed (same as R8): index = ((((tap*8+g)*4+wn)*8+lr)*8+kq)*4+ns
// u32 = half2(ci, ci+1), co = wn*32+ns*8+lr, ci = g*16+2*kq.
__device__ unsigned int Wf[9 * 8 * 4 * 8 * 8 * 4];   // 73728 u32

#define PST 68                        // u32 per pos row; 68%32==4
#define SMEM_BYTES (324 * PST * 4)    // 88,128 B

static __device__ __forceinline__ uint32_t packh2(float a, float b) {
    __half2 h = __floats2half2_rn(a, b);
    return *reinterpret_cast<uint32_t*>(&h);
}

static __device__ __forceinline__ void mma_fp16(float* c, const uint32_t* a,
                                                uint32_t b0, uint32_t b1) {
    asm volatile(
        "mma.sync.aligned.m16n8k16.row.col.f32.f16.f16.f32 "
        "{%0,%1,%2,%3}, {%4,%5,%6,%7}, {%8,%9}, {%0,%1,%2,%3};"
        : "+f"(c[0]), "+f"(c[1]), "+f"(c[2]), "+f"(c[3])
        : "r"(a[0]), "r"(a[1]), "r"(a[2]), "r"(a[3]), "r"(b0), "r"(b1));
}

static __device__ __forceinline__ void ldsm_x4(uint32_t* A, uint32_t addr) {
    asm volatile(
        "ldmatrix.sync.aligned.m8n8.x4.shared.b16 {%0,%1,%2,%3}, [%4];"
        : "=r"(A[0]), "=r"(A[1]), "=r"(A[2]), "=r"(A[3]) : "r"(addr));
}

// ---------------- prep: W -> Wf (unchanged from R8) ----------------
__global__ void prep_w_kernel(const float* __restrict__ W) {
    int idx = blockIdx.x * 256 + threadIdx.x;
    if (idx >= 73728) return;
    int ns  = idx & 3;
    int kq  = (idx >> 2) & 7;
    int lr  = (idx >> 5) & 7;
    int wn  = (idx >> 8) & 3;
    int g   = (idx >> 10) & 7;
    int tap = idx >> 13;
    int co  = wn * 32 + ns * 8 + lr;
    int ci  = g * 16 + kq * 2;
    Wf[idx] = packh2(W[co * 1152 + ci * 9 + tap],
                     W[co * 1152 + (ci + 1) * 9 + tap]);
}

// ---------------- main ----------------
__global__ void __launch_bounds__(512, 1)
kagome_mma_kernel(const float* __restrict__ x,
                  const float* __restrict__ b,
                  float* __restrict__ out) {
    extern __shared__ uint32_t xpm[];   // [324 pos][PST u32]

    const int tid   = threadIdx.x;
    const int wid   = tid >> 5;
    const int lane  = tid & 31;
    const int q     = lane & 3;
    const int lr    = lane >> 2;
    const int warpM = wid & 3;          // 4 groups of 4 image rows (64 px)
    const int warpN = wid >> 2;         // 4 groups of 32 co
    const int img   = blockIdx.x;

    const float* xg = x + (size_t)img * 128 * 256;

    // ---- zero the 68-position pad ring (interior fully overwritten) ----
    for (int j = tid; j < 68 * 17; j += 512) {
        int ri = j / 17, ch = j - ri * 17;       // PST=68 u32 = 17 uint4
        int pos;
        if (ri < 18)       pos = ri;                      // row 0
        else if (ri < 36)  pos = 17 * 18 + (ri - 18);     // row 17
        else if (ri < 52)  pos = (ri - 35) * 18;          // col 0, rows 1..16
        else               pos = (ri - 51) * 18 + 17;     // col 17, rows 1..16
        *(uint4*)(xpm + pos * PST + ch * 4) = make_uint4(0, 0, 0, 0);
    }
    // ---- interior: pos-major, u32 j = half2(ci 2j, 2j+1) ----
    #pragma unroll
    for (int i = 0; i < 8; i++) {
        int idx = tid + i * 512;            // 0..4095
        int p   = idx >> 6;                 // ci pair 0..63
        int px4 = (idx & 63) << 2;          // 0,4,...,252 (within one row)
        float4 r0 = *(const float4*)(xg + (2 * p) * 256 + px4);
        float4 r1 = *(const float4*)(xg + (2 * p + 1) * 256 + px4);
        int pos = ((px4 >> 4) + 1) * 18 + (px4 & 15) + 1;
        uint32_t* d = xpm + pos * PST + p;
        d[0]       = packh2(r0.x, r1.x);
        d[PST]     = packh2(r0.y, r1.y);
        d[2 * PST] = packh2(r0.z, r1.z);
        d[3 * PST] = packh2(r0.w, r1.w);
    }
    __syncthreads();   // interior visible before fixups overwrite
    // ---- 37 boundary fixups per ci pair ----
    for (int j = tid; j < 64 * 37; j += 512) {
        int p = j / 37, f = j - p * 37;
        int spx = (FSR[f] - 1) * 16 + (FSC[f] - 1);
        xpm[(FDR[f] * 18 + FDC[f]) * PST + p] =
            packh2(xg[(2 * p) * 256 + spx], xg[(2 * p + 1) * 256 + spx]);
    }
    __syncthreads();

    // ---- mainloop: 72 iterations (9 taps x 8 ci-groups) ----
    float C[4][4][4];
    #pragma unroll
    for (int s = 0; s < 4; s++)
        #pragma unroll
        for (int n = 0; n < 4; n++)
            #pragma unroll
            for (int e = 0; e < 4; e++) C[s][n][e] = 0.f;

    const uint32_t sb = (uint32_t)__cvta_generic_to_shared(xpm);
    // per-lane ldmatrix offset: col = lane&15 (pos), k-half = lane>>4
    const uint32_t laneoff = (((lane & 15) * PST) + (lane >> 4) * 4) * 4;

    const uint32_t* wbase = Wf + ((warpN * 8) + lr) * 32 + q * 4;
    uint4 Bs[2][2];
    Bs[0][0] = __ldg((const uint4*)(wbase));
    Bs[0][1] = __ldg((const uint4*)(wbase + 16));
    Bs[1][0] = __ldg((const uint4*)(wbase + 1024));
    Bs[1][1] = __ldg((const uint4*)(wbase + 1024 + 16));

    #pragma unroll 2
    for (int u = 0; u < 72; u++) {
        const int tap = u >> 3, g = u & 7;
        const int kr = (tap >= 6) ? 2 : (tap >= 3 ? 1 : 0);
        const int toff = kr * 18 + (tap - kr * 3);   // kr*18 + kc

        uint4 b0 = Bs[u & 1][0];
        uint4 b1 = Bs[u & 1][1];
        if (u < 70) {
            const uint32_t* wp = wbase + (u + 2) * 1024;
            Bs[u & 1][0] = __ldg((const uint4*)(wp));
            Bs[u & 1][1] = __ldg((const uint4*)(wp + 16));
        }

        #pragma unroll
        for (int s = 0; s < 4; s++) {
            int R = warpM * 4 + s;
            uint32_t addr = sb + (uint32_t)(((R * 18 + toff) * PST + g * 8) * 4)
                          + laneoff;
            uint32_t A[4];
            ldsm_x4(A, addr);
            mma_fp16(C[s][0], A, b0.x, b1.x);
            mma_fp16(C[s][1], A, b0.y, b1.y);
            mma_fp16(C[s][2], A, b0.z, b1.z);
            mma_fp16(C[s][3], A, b0.w, b1.w);
        }
    }

    // ---- epilogue: +bias, *mask, store ----
    float* og = out + (size_t)img * 128 * 256;
    #pragma unroll
    for (int ns = 0; ns < 4; ns++) {
        int co0 = warpN * 32 + ns * 8 + 2 * q;
        float bv0 = __ldg(b + co0);
        float bv1 = __ldg(b + co0 + 1);
        #pragma unroll
        for (int s = 0; s < 4; s++) {
            int R = warpM * 4 + s;
            unsigned mrow = (R == 13) ? MASKROW_FIX : MASKROW[R];
            float k0 = ((mrow >> lr) & 1u) ? 1.f : 0.f;
            float k1 = ((mrow >> (lr + 8)) & 1u) ? 1.f : 0.f;
            int p0 = R * 16 + lr;
            int p1 = p0 + 8;
            og[co0 * 256 + p0]       = (C[s][ns][0] + bv0) * k0;
            og[(co0 + 1) * 256 + p0] = (C[s][ns][1] + bv1) * k0;
            og[co0 * 256 + p1]       = (C[s][ns][2] + bv0) * k1;
            og[(co0 + 1) * 256 + p1] = (C[s][ns][3] + bv1) * k1;
        }
    }
}

extern "C" void kernel_launch(void* const* d_in, const int* in_sizes, int n_in,
                              void* d_out, int out_size) {
    (void)in_sizes; (void)n_in; (void)out_size;
    const float* x = (const float*)d_in[0];
    const float* W = (const float*)d_in[1];
    const float* b = (const float*)d_in[2];
    float* out = (float*)d_out;

    cudaFuncSetAttribute(kagome_mma_kernel,
                         cudaFuncAttributeMaxDynamicSharedMemorySize, SMEM_BYTES);

    prep_w_kernel<<<288, 256>>>(W);
    kagome_mma_kernel<<<2048, 512, SMEM_BYTES>>>(x, b, out);
}